// round 8
// baseline (speedup 1.0000x reference)
#include <cuda_runtime.h>
#include <cuda_bf16.h>
#include <cstdint>

#define NUM_E 16
#define D_IN  2048
#define D_OUT 8192
#define T_TOK 8192

// CTA tile 128(M) x 128(N), K-chunk 32. 4 warps = 2(M) x 2(N), warp tile 64x64.
// Double-buffered smem (64KB), 2 CTAs/SM via 128-thread CTAs.
#define BM 128
#define BN 128
#define BK 32
#define NCHUNK (D_IN / BK)   // 64
#define THREADS 128

// Packed smem: per k16-half region = 128 rows x 32B (4KB), XOR-swizzled.
#define REG_SZ  4096
#define A_HI    0
#define A_LO    8192
#define B_HI    16384
#define B_LO    24576
#define STAGE_B 32768
#define SMEM_BYTES (2 * STAGE_B)   // 65536

__device__ __forceinline__ uint32_t swz(uint32_t a) {
    return a ^ ((a & 128u) >> 3);
}

__device__ __forceinline__ uint32_t smem_u32_of(const void* p) {
    uint32_t a;
    asm("{ .reg .u64 t; cvta.to.shared.u64 t, %1; cvt.u32.u64 %0, t; }" : "=r"(a) : "l"(p));
    return a;
}

__device__ __forceinline__ uint32_t pack2(__nv_bfloat16 a, __nv_bfloat16 b) {
    __nv_bfloat162 t = __halves2bfloat162(a, b);
    return *reinterpret_cast<uint32_t*>(&t);
}

__device__ __forceinline__ void sts8(uint32_t addr, uint32_t x, uint32_t y) {
    asm volatile("st.shared.v2.b32 [%0], {%1, %2};" :: "r"(addr), "r"(x), "r"(y) : "memory");
}

__device__ __forceinline__ void split_store4(float4 v, uint32_t hi_addr, uint32_t lo_addr) {
    __nv_bfloat16 h0 = __float2bfloat16(v.x);
    __nv_bfloat16 h1 = __float2bfloat16(v.y);
    __nv_bfloat16 h2 = __float2bfloat16(v.z);
    __nv_bfloat16 h3 = __float2bfloat16(v.w);
    __nv_bfloat16 l0 = __float2bfloat16(v.x - __bfloat162float(h0));
    __nv_bfloat16 l1 = __float2bfloat16(v.y - __bfloat162float(h1));
    __nv_bfloat16 l2 = __float2bfloat16(v.z - __bfloat162float(h2));
    __nv_bfloat16 l3 = __float2bfloat16(v.w - __bfloat162float(h3));
    sts8(hi_addr, pack2(h0, h1), pack2(h2, h3));
    sts8(lo_addr, pack2(l0, l1), pack2(l2, l3));
}

__device__ __forceinline__ void ldsm_x4(uint32_t* r, uint32_t addr) {
    asm volatile("ldmatrix.sync.aligned.m8n8.x4.shared.b16 {%0,%1,%2,%3}, [%4];"
                 : "=r"(r[0]), "=r"(r[1]), "=r"(r[2]), "=r"(r[3]) : "r"(addr));
}

__device__ __forceinline__ void mma_bf16(float* d, const uint32_t* a, uint32_t b0, uint32_t b1) {
    asm volatile(
        "mma.sync.aligned.m16n8k16.row.col.f32.bf16.bf16.f32 "
        "{%0,%1,%2,%3}, {%4,%5,%6,%7}, {%8,%9}, {%0,%1,%2,%3};"
        : "+f"(d[0]), "+f"(d[1]), "+f"(d[2]), "+f"(d[3])
        : "r"(a[0]), "r"(a[1]), "r"(a[2]), "r"(a[3]), "r"(b0), "r"(b1));
}

// One k16 step: load B hi+lo and A hi -> terms hh, hl; reload A as lo -> term lh.
__device__ __forceinline__ void k16_step(uint32_t hb, int warp_m, int warp_n,
                                         int a_row, int a_c2, int b_row, int b_c2,
                                         float d[4][8][4])
{
    uint32_t bh[4][4], bl[4][4];
    #pragma unroll
    for (int nb = 0; nb < 4; nb++) {
        uint32_t a = swz((uint32_t)((warp_n + nb * 16 + b_row) * 32 + b_c2 * 16));
        ldsm_x4(bh[nb], hb + B_HI + a);
        ldsm_x4(bl[nb], hb + B_LO + a);
    }
    {
        uint32_t af[4][4];
        #pragma unroll
        for (int f = 0; f < 4; f++) {
            uint32_t a = swz((uint32_t)((warp_m + f * 16 + a_row) * 32 + a_c2 * 16));
            ldsm_x4(af[f], hb + A_HI + a);
        }
        #pragma unroll
        for (int f = 0; f < 4; f++)
            #pragma unroll
            for (int nb = 0; nb < 4; nb++) {
                mma_bf16(d[f][nb * 2 + 0], af[f], bh[nb][0], bh[nb][1]);
                mma_bf16(d[f][nb * 2 + 1], af[f], bh[nb][2], bh[nb][3]);
            }
        #pragma unroll
        for (int f = 0; f < 4; f++)
            #pragma unroll
            for (int nb = 0; nb < 4; nb++) {
                mma_bf16(d[f][nb * 2 + 0], af[f], bl[nb][0], bl[nb][1]);
                mma_bf16(d[f][nb * 2 + 1], af[f], bl[nb][2], bl[nb][3]);
            }
    }
    {
        uint32_t af[4][4];
        #pragma unroll
        for (int f = 0; f < 4; f++) {
            uint32_t a = swz((uint32_t)((warp_m + f * 16 + a_row) * 32 + a_c2 * 16));
            ldsm_x4(af[f], hb + A_LO + a);
        }
        #pragma unroll
        for (int f = 0; f < 4; f++)
            #pragma unroll
            for (int nb = 0; nb < 4; nb++) {
                mma_bf16(d[f][nb * 2 + 0], af[f], bh[nb][0], bh[nb][1]);
                mma_bf16(d[f][nb * 2 + 1], af[f], bh[nb][2], bh[nb][3]);
            }
    }
}

__global__ __launch_bounds__(THREADS, 2)
void moe_gemm_mma6_kernel(const float* __restrict__ inp,     // [T, D_IN]
                          const float* __restrict__ weight,  // [E, D_OUT, D_IN]
                          const float* __restrict__ bias,    // [E, D_OUT]
                          const int*   __restrict__ cnt,     // [E]
                          float*       __restrict__ out)     // [T, D_OUT]
{
    extern __shared__ char smem[];
    const uint32_t sbase = smem_u32_of(smem);

    const int tid = threadIdx.x;
    const int wid = tid >> 5;
    const int lid = tid & 31;

    const int nBase = blockIdx.x * BN;
    const int mBase = blockIdx.y * BM;

    int e = 0;
    {
        int acc = 0;
        #pragma unroll
        for (int i = 0; i < NUM_E; i++) {
            int c = cnt[i];
            if (mBase >= acc + c) { acc += c; e = i + 1; }
        }
    }
    const float* wptr = weight + (size_t)e * D_OUT * D_IN;

    // 4 warps: 2(M) x 2(N); warp tile 64x64
    const int warp_m = (wid >> 1) * 64;
    const int warp_n = (wid & 1) * 64;

    const int a_row = (lid & 7) + ((lid >> 3) & 1) * 8;
    const int a_c2  = (lid >> 4) & 1;
    const int b_row = (lid & 7) + ((lid >> 4) & 1) * 8;
    const int b_c2  = (lid >> 3) & 1;

    // Staging: 128 rows x 32 fp32 per matrix; warp inst covers 4 rows x 128B.
    // thread: row = wid*4 + (lid>>3) + r*16, quad = lid&7; 8 rounds per matrix.
    const int srow = wid * 4 + (lid >> 3);
    const int quad = lid & 7;
    const uint32_t piece = swz((uint32_t)(srow * 32 + (quad & 3) * 8));
    const uint32_t half_off = (uint32_t)((quad >> 2) * REG_SZ);

    const float* aG = inp  + (size_t)(mBase + srow) * D_IN + quad * 4;
    const float* bG = wptr + (size_t)(nBase + srow) * D_IN + quad * 4;

    float d[4][8][4];
    #pragma unroll
    for (int f = 0; f < 4; f++)
        #pragma unroll
        for (int n = 0; n < 8; n++)
            #pragma unroll
            for (int k = 0; k < 4; k++)
                d[f][n][k] = 0.0f;

    // ---- prologue: chunk 0 into stage 0 ----
    {
        float4 s[8];
        #pragma unroll
        for (int r = 0; r < 8; r++)
            s[r] = *reinterpret_cast<const float4*>(aG + (size_t)(r * 16) * D_IN);
        #pragma unroll
        for (int r = 0; r < 8; r++) {
            uint32_t off = half_off + piece + (uint32_t)(r * 512);
            split_store4(s[r], sbase + A_HI + off, sbase + A_LO + off);
        }
        #pragma unroll
        for (int r = 0; r < 8; r++)
            s[r] = *reinterpret_cast<const float4*>(bG + (size_t)(r * 16) * D_IN);
        #pragma unroll
        for (int r = 0; r < 8; r++) {
            uint32_t off = half_off + piece + (uint32_t)(r * 512);
            split_store4(s[r], sbase + B_HI + off, sbase + B_LO + off);
        }
    }
    __syncthreads();

    #pragma unroll 1
    for (int i = 0; i < NCHUNK; i++) {
        const uint32_t cur = sbase + (uint32_t)(i & 1) * STAGE_B;
        const uint32_t nxt = sbase + (uint32_t)((i + 1) & 1) * STAGE_B;
        const bool pf = (i + 1 < NCHUNK);
        const int kb = (i + 1) * BK;

        // prefetch next A into registers, hide under k16 step 0
        float4 aS[8];
        if (pf) {
            #pragma unroll
            for (int r = 0; r < 8; r++)
                aS[r] = *reinterpret_cast<const float4*>(aG + kb + (size_t)(r * 16) * D_IN);
        }

        k16_step(cur, warp_m, warp_n, a_row, a_c2, b_row, b_c2, d);

        float4 bS[8];
        if (pf) {
            #pragma unroll
            for (int r = 0; r < 8; r++) {
                uint32_t off = half_off + piece + (uint32_t)(r * 512);
                split_store4(aS[r], nxt + A_HI + off, nxt + A_LO + off);
            }
            #pragma unroll
            for (int r = 0; r < 8; r++)
                bS[r] = *reinterpret_cast<const float4*>(bG + kb + (size_t)(r * 16) * D_IN);
        }

        k16_step(cur + REG_SZ, warp_m, warp_n, a_row, a_c2, b_row, b_c2, d);

        if (pf) {
            #pragma unroll
            for (int r = 0; r < 8; r++) {
                uint32_t off = half_off + piece + (uint32_t)(r * 512);
                split_store4(bS[r], nxt + B_HI + off, nxt + B_LO + off);
            }
        }
        __syncthreads();
    }

    // ---- epilogue: bias + fp32 store ----
    const int g  = lid >> 2;
    const int t4 = lid & 3;
    const float* brow = bias + (size_t)e * D_OUT;
    #pragma unroll
    for (int f = 0; f < 4; f++) {
        const int row0 = mBase + warp_m + f * 16 + g;
        #pragma unroll
        for (int nf = 0; nf < 8; nf++) {
            const int col = nBase + warp_n + nf * 8 + t4 * 2;
            float2 bv = *reinterpret_cast<const float2*>(brow + col);
            float2 o0, o1;
            o0.x = d[f][nf][0] + bv.x;
            o0.y = d[f][nf][1] + bv.y;
            o1.x = d[f][nf][2] + bv.x;
            o1.y = d[f][nf][3] + bv.y;
            *reinterpret_cast<float2*>(out + (size_t)row0 * D_OUT + col) = o0;
            *reinterpret_cast<float2*>(out + (size_t)(row0 + 8) * D_OUT + col) = o1;
        }
    }
}

extern "C" void kernel_launch(void* const* d_in, const int* in_sizes, int n_in,
                              void* d_out, int out_size)
{
    const float* inp    = (const float*)d_in[0];
    const float* weight = (const float*)d_in[1];
    const float* bias   = (const float*)d_in[2];
    const int*   cnt    = (const int*)d_in[3];
    float* out = (float*)d_out;

    cudaFuncSetAttribute(moe_gemm_mma6_kernel,
                         cudaFuncAttributeMaxDynamicSharedMemorySize, SMEM_BYTES);

    dim3 grid(D_OUT / BN, T_TOK / BM);   // (64, 64)
    moe_gemm_mma6_kernel<<<grid, THREADS, SMEM_BYTES>>>(inp, weight, bias, cnt, out);
}